// round 12
// baseline (speedup 1.0000x reference)
#include <cuda_runtime.h>
#include <cstdint>

// Problem shape
#define BB      16
#define TT      4096
#define UU      1024
#define TC      16                 // t-rows per chunk
#define RR      4                  // rows held in registers
#define SR      12                 // rows via cp.async into smem (column-private)
#define NC      (TT / TC)          // 256 chunks per batch chain
#define U4      (UU / 4)           // 256 float4 per row
#define THREADS 256                // one thread per float4 column
#define NWARP   8
#define NTICK   (BB * NC)
#define FACTOR  0.5f

// Decoupled-lookback scratch (device globals: no allocation allowed).
__device__ float4 g_agg[NTICK * U4];            // 16 MiB
__device__ float4 g_inc[NTICK * U4];            // 16 MiB
// Flags: 0 = invalid, 1 = aggregate ready, 2 = inclusive ready.
// Last slot doubles as the dynamic-ticket counter.
__device__ unsigned int g_flags[NTICK + 1];
// Last-arriver warp counters for agg / inc publication.
__device__ unsigned int g_cnta[NTICK];
__device__ unsigned int g_cnti[NTICK];

__device__ __forceinline__ void st_release_gpu(unsigned int* p, unsigned int v) {
    asm volatile("st.release.gpu.u32 [%0], %1;" :: "l"(p), "r"(v) : "memory");
}
__device__ __forceinline__ unsigned int ld_acquire_gpu(const unsigned int* p) {
    unsigned int v;
    asm volatile("ld.acquire.gpu.u32 %0, [%1];" : "=r"(v) : "l"(p) : "memory");
    return v;
}
__device__ __forceinline__ unsigned int atom_add_acq_rel(unsigned int* p, unsigned int v) {
    unsigned int old;
    asm volatile("atom.acq_rel.gpu.add.u32 %0, [%1], %2;"
                 : "=r"(old) : "l"(p), "r"(v) : "memory");
    return old;
}
__device__ __forceinline__ void cp_async16(uint32_t saddr, const void* gaddr) {
    asm volatile("cp.async.cg.shared.global [%0], [%1], 16;" :: "r"(saddr), "l"(gaddr));
}

// One warp-wide poll of predecessors [base_p-31 .. base_p].
// All lanes return identical (D, fin) computed from ballots.
__device__ __forceinline__ void poll_window(const unsigned int* flags_chain, int base_p,
                                            int lane, int& D, int& fin) {
    const int p = base_p - lane;
    const unsigned f = (p >= 0) ? ld_acquire_gpu(&flags_chain[p]) : 0u;
    const unsigned b1 = __ballot_sync(0xffffffffu, f >= 1u);
    const unsigned b2 = __ballot_sync(0xffffffffu, f == 2u);
    const int k = __ffs(~b1);                    // first not-ready lane (+1); 0 => all ready
    const int nready = (k == 0) ? 32 : (k - 1);
    const int l2 = __ffs(b2) - 1;                // nearest inclusive; -1 if none
    if (l2 >= 0 && l2 <= nready) { fin = 1; D = l2; }
    else                         { fin = 0; D = nready; }
}

__global__ __launch_bounds__(THREADS, 4)
void rac_scan_kernel(const float4* __restrict__ xv,
                     const float4* __restrict__ h0v,
                     float4* __restrict__ outv) {
    __shared__ float4 s_tile[SR * THREADS];   // 48 KB, column-private per thread
    __shared__ unsigned int s_vb;

    const int tid  = threadIdx.x;
    const int lane = tid & 31;

    // Dynamic ticket (the ONLY block-wide barrier in the kernel).
    if (tid == 0) s_vb = atomicAdd(&g_flags[NTICK], 1u);
    __syncthreads();
    const unsigned int vb = s_vb;
    const int b = vb & (BB - 1);   // batch fastest -> all 16 chains advance together
    const int c = vb >> 4;

    const size_t base = ((size_t)b * TT + (size_t)c * TC) * U4 + tid;

    // Rows RR..TC-1 -> smem via cp.async (per-thread groups, column-private).
    const uint32_t sbase = (uint32_t)__cvta_generic_to_shared(&s_tile[tid]);
#pragma unroll
    for (int t = 0; t < SR; t++)
        cp_async16(sbase + t * (THREADS * 16),
                   (const void*)(xv + base + (size_t)(RR + t) * U4));
    asm volatile("cp.async.commit_group;" ::: "memory");

    const float4 h = h0v[b * U4 + tid];

    // Rows 0..RR-1 -> registers (streamed), prefixed.
    float4 v[RR];
#pragma unroll
    for (int t = 0; t < RR; t++) v[t] = __ldcs(&xv[base + (size_t)t * U4]);
#pragma unroll
    for (int t = 1; t < RR; t++) {
        v[t].x += v[t - 1].x;
        v[t].y += v[t - 1].y;
        v[t].z += v[t - 1].z;
        v[t].w += v[t - 1].w;
    }

    const int chain = b * NC;
    unsigned int* flags_chain = &g_flags[chain];
    const int fidx = chain + c;
    const int sidx = fidx * U4 + tid;
    const bool is_last = (c == NC - 1);
    float4 excl = make_float4(0.f, 0.f, 0.f, 0.f);

    // ---- Per-warp pre-phase lookback (non-blocking), overlapped with cp.async. ----
    int base_p = c - 1;
    bool done = (c == 0);
    while (!done) {
        int D, fin;
        poll_window(flags_chain, base_p, lane, D, fin);
        if (!fin && D == 0) break;            // no progress -> consume our data first
        __syncwarp();                          // HB: lanes' flag-acquires -> my data loads
        for (int l = 0; l < D; l++) {
            const float4 a = __ldcg(&g_agg[(chain + base_p - l) * U4 + tid]);
            excl.x += a.x; excl.y += a.y; excl.z += a.z; excl.w += a.w;
        }
        if (fin) {
            const float4 a = __ldcg(&g_inc[(chain + base_p - D) * U4 + tid]);
            excl.x += a.x; excl.y += a.y; excl.z += a.z; excl.w += a.w;
            done = true;
            break;
        }
        base_p -= D;
    }

    // ---- Wait own cp.async; local prefix over smem rows (column-private). ----
    asm volatile("cp.async.wait_group 0;" ::: "memory");
    float4 run = make_float4(0.f, 0.f, 0.f, 0.f);
#pragma unroll
    for (int t = 0; t < SR; t++) {
        const float4 a = s_tile[t * THREADS + tid];
        run.x += a.x; run.y += a.y; run.z += a.z; run.w += a.w;
        s_tile[t * THREADS + tid] = run;
    }
    float4 agg;
    agg.x = v[RR - 1].x + run.x;
    agg.y = v[RR - 1].y + run.y;
    agg.z = v[RR - 1].z + run.z;
    agg.w = v[RR - 1].w + run.w;

    if (!done) {
        // Publish aggregate slice; last-arriving warp raises flag=1.
        if (!is_last) {
            g_agg[sidx] = agg;
            __syncwarp();                      // fence lanes' stores before lane0's release-add
            if (lane == 0) {
                if (atom_add_acq_rel(&g_cnta[fidx], 1u) == NWARP - 1)
                    st_release_gpu(&g_flags[fidx], 1u);
            }
        }
        // ---- Per-warp residual lookback (blocking). ----
        for (;;) {
            int D, fin;
            poll_window(flags_chain, base_p, lane, D, fin);
            __syncwarp();
            for (int l = 0; l < D; l++) {
                const float4 a = __ldcg(&g_agg[(chain + base_p - l) * U4 + tid]);
                excl.x += a.x; excl.y += a.y; excl.z += a.z; excl.w += a.w;
            }
            if (fin) {
                const float4 a = __ldcg(&g_inc[(chain + base_p - D) * U4 + tid]);
                excl.x += a.x; excl.y += a.y; excl.z += a.z; excl.w += a.w;
                break;
            }
            base_p -= D;
        }
    }

    // Publish inclusive slice; last-arriving warp raises flag=2.
    if (!is_last) {
        float4 inc;
        inc.x = excl.x + agg.x; inc.y = excl.y + agg.y;
        inc.z = excl.z + agg.z; inc.w = excl.w + agg.w;
        g_inc[sidx] = inc;
        __syncwarp();
        if (lane == 0) {
            if (atom_add_acq_rel(&g_cnti[fidx], 1u) == NWARP - 1)
                st_release_gpu(&g_flags[fidx], 2u);
        }
    }

    // ---- Epilogue: out = h0 + FACTOR * (exclusive + local_prefix) ----
#pragma unroll
    for (int t = 0; t < RR; t++) {
        float4 o;
        o.x = h.x + FACTOR * (excl.x + v[t].x);
        o.y = h.y + FACTOR * (excl.y + v[t].y);
        o.z = h.z + FACTOR * (excl.z + v[t].z);
        o.w = h.w + FACTOR * (excl.w + v[t].w);
        __stcs(&outv[base + (size_t)t * U4], o);
    }
    const float4 lo = v[RR - 1];
#pragma unroll
    for (int t = 0; t < SR; t++) {
        const float4 p = s_tile[t * THREADS + tid];
        float4 o;
        o.x = h.x + FACTOR * (excl.x + lo.x + p.x);
        o.y = h.y + FACTOR * (excl.y + lo.y + p.y);
        o.z = h.z + FACTOR * (excl.z + lo.z + p.z);
        o.w = h.w + FACTOR * (excl.w + lo.w + p.w);
        __stcs(&outv[base + (size_t)(RR + t) * U4], o);
    }
}

extern "C" void kernel_launch(void* const* d_in, const int* in_sizes, int n_in,
                              void* d_out, int out_size) {
    (void)in_sizes; (void)n_in; (void)out_size;
    const float4* xv  = (const float4*)d_in[0];   // x:  (16, 4096, 1024) f32
    const float4* h0v = (const float4*)d_in[1];   // h0: (16, 1024) f32
    float4* outv      = (float4*)d_out;           // out:(16, 4096, 1024) f32

    // Reset flags + ticket + warp counters every launch (captured memset nodes).
    void* p = nullptr;
    cudaGetSymbolAddress(&p, g_flags);
    cudaMemsetAsync(p, 0, (NTICK + 1) * sizeof(unsigned int), 0);
    cudaGetSymbolAddress(&p, g_cnta);
    cudaMemsetAsync(p, 0, NTICK * sizeof(unsigned int), 0);
    cudaGetSymbolAddress(&p, g_cnti);
    cudaMemsetAsync(p, 0, NTICK * sizeof(unsigned int), 0);

    rac_scan_kernel<<<NTICK, THREADS>>>(xv, h0v, outv);
}